// round 4
// baseline (speedup 1.0000x reference)
#include <cuda_runtime.h>
#include <cuda_bf16.h>
#include <cstdint>

// Problem constants
#define B_   2
#define S_   2048
#define D_   1024
#define H_   16
#define DH_  64
#define N_   (B_ * S_)   // 4096 tokens
#define K_   1024

// ---------------------------------------------------------------------------
// Scratch (device globals — no allocation allowed)
// ---------------------------------------------------------------------------
__device__ float g_q[B_ * H_ * S_ * DH_];   // [b][h][s][dh]
__device__ float g_k[B_ * H_ * S_ * DH_];
__device__ float g_v[B_ * H_ * S_ * DH_];
__device__ float g_att[N_ * D_];            // [n][h*64+dh]

// ---------------------------------------------------------------------------
// tf32 helpers (baseline PTX — no arch-suffix features)
// ---------------------------------------------------------------------------
__device__ __forceinline__ uint32_t f2tf32(float f) {
    uint32_t u;
    asm("cvt.rna.tf32.f32 %0, %1;" : "=r"(u) : "f"(f));
    return u;
}

__device__ __forceinline__ void mma_tf32(float* c, const uint32_t* a, const uint32_t* b) {
    asm volatile(
        "mma.sync.aligned.m16n8k8.row.col.f32.tf32.tf32.f32 "
        "{%0,%1,%2,%3}, {%4,%5,%6,%7}, {%8,%9}, {%0,%1,%2,%3};"
        : "+f"(c[0]), "+f"(c[1]), "+f"(c[2]), "+f"(c[3])
        : "r"(a[0]), "r"(a[1]), "r"(a[2]), "r"(a[3]), "r"(b[0]), "r"(b[1]));
}

// ---------------------------------------------------------------------------
// Tensor-core (HMMA tf32) TN GEMM: C[n,o] = sum_k A[n,k]*W[o,k] + bias[o]
// A:[4096,1024], W:[1024,1024], K-major both. Tile 128x128x32, 256 threads.
// scatter==1 -> Q/K/V head-major layout, else row-major.
// ---------------------------------------------------------------------------
#define KPAD 36   // padded k-stride (floats): frag LDS conflict-free

__global__ void __launch_bounds__(256, 2)
gemm_mma_tf32(const float* __restrict__ A, const float* __restrict__ W,
              const float* __restrict__ bias, float* __restrict__ C, int scatter)
{
    __shared__ uint32_t As[128 * KPAD];
    __shared__ uint32_t Bs[128 * KPAD];

    const int tid  = threadIdx.x;
    const int wid  = tid >> 5;
    const int lane = tid & 31;
    const int bn = blockIdx.x;   // o block (8)
    const int bm = blockIdx.y;   // token block (32)

    const int wr = (wid & 1) << 6;   // warp m offset: 0 / 64
    const int wc = (wid >> 1) << 5;  // warp n offset: 0..96

    // gmem load mapping: row = tid>>3 (+32i), kc = (tid&7)*4
    const int lrow = tid >> 3;          // 0..31
    const int lkc  = (tid & 7) << 2;    // 0..28

    const float* Ag = A + (size_t)(bm * 128 + lrow) * K_ + lkc;
    const float* Bg = W + (size_t)(bn * 128 + lrow) * K_ + lkc;

    float acc[4][4][4];
#pragma unroll
    for (int t = 0; t < 4; t++)
#pragma unroll
        for (int j = 0; j < 4; j++)
#pragma unroll
            for (int r = 0; r < 4; r++) acc[t][j][r] = 0.f;

    float4 pa[4], pb[4];
#pragma unroll
    for (int i = 0; i < 4; i++) {
        pa[i] = *(const float4*)(Ag + (size_t)(32 * i) * K_);
        pb[i] = *(const float4*)(Bg + (size_t)(32 * i) * K_);
    }

    const int la = lane >> 2;   // 0..7
    const int lb = lane & 3;    // 0..3

    for (int c = 0; c < 32; c++) {
        __syncthreads();
        // store prefetched chunk (convert to tf32-rna bits)
#pragma unroll
        for (int i = 0; i < 4; i++) {
            const int so = (lrow + 32 * i) * KPAD + lkc;
            As[so + 0] = f2tf32(pa[i].x); As[so + 1] = f2tf32(pa[i].y);
            As[so + 2] = f2tf32(pa[i].z); As[so + 3] = f2tf32(pa[i].w);
            Bs[so + 0] = f2tf32(pb[i].x); Bs[so + 1] = f2tf32(pb[i].y);
            Bs[so + 2] = f2tf32(pb[i].z); Bs[so + 3] = f2tf32(pb[i].w);
        }
        __syncthreads();
        if (c < 31) {
            const size_t ko = (size_t)(c + 1) * 32;
#pragma unroll
            for (int i = 0; i < 4; i++) {
                pa[i] = *(const float4*)(Ag + (size_t)(32 * i) * K_ + ko);
                pb[i] = *(const float4*)(Bg + (size_t)(32 * i) * K_ + ko);
            }
        }
        // compute: 4 k-steps of 8
#pragma unroll
        for (int ks = 0; ks < 4; ks++) {
            const int k0 = ks * 8 + lb;
            uint32_t af[4][4];
#pragma unroll
            for (int t = 0; t < 4; t++) {
                const int r0 = (wr + t * 16 + la) * KPAD;
                af[t][0] = As[r0 + k0];
                af[t][1] = As[r0 + 8 * KPAD + k0];
                af[t][2] = As[r0 + k0 + 4];
                af[t][3] = As[r0 + 8 * KPAD + k0 + 4];
            }
            uint32_t bf[4][2];
#pragma unroll
            for (int j = 0; j < 4; j++) {
                const int cj = (wc + j * 8 + la) * KPAD;
                bf[j][0] = Bs[cj + k0];
                bf[j][1] = Bs[cj + k0 + 4];
            }
#pragma unroll
            for (int t = 0; t < 4; t++)
#pragma unroll
                for (int j = 0; j < 4; j++)
                    mma_tf32(acc[t][j], af[t], bf[j]);
        }
    }

    // Epilogue: c0,c1 at (row, 2q), (row, 2q+1); c2,c3 at row+8
    const int rbase = bm * 128 + wr + la;
    const int cbase = bn * 128 + wc + 2 * lb;
#pragma unroll
    for (int t = 0; t < 4; t++) {
#pragma unroll
        for (int j = 0; j < 4; j++) {
            const int col = cbase + j * 8;
            const float bx = bias[col], by = bias[col + 1];
#pragma unroll
            for (int h2 = 0; h2 < 2; h2++) {   // row / row+8
                const int n = rbase + t * 16 + 8 * h2;
                float2 v;
                v.x = acc[t][j][2 * h2 + 0] + bx;
                v.y = acc[t][j][2 * h2 + 1] + by;
                if (scatter) {
                    const int b  = n >> 11;
                    const int s  = n & (S_ - 1);
                    const int hh = col >> 6;
                    const int dh = col & 63;
                    *(float2*)(C + (((size_t)(b * H_ + hh)) * S_ + s) * DH_ + dh) = v;
                } else {
                    *(float2*)(C + (size_t)n * D_ + col) = v;
                }
            }
        }
    }
}

// ---------------------------------------------------------------------------
// Flash attention (unchanged — fp32, at FFMA roofline)
// ---------------------------------------------------------------------------
#define FP 68

__global__ void __launch_bounds__(256)
flash_kernel(const int* __restrict__ mask, float* __restrict__ out)
{
    extern __shared__ float smf[];
    float* Qt = smf;
    float* Kt = Qt + 64 * FP;
    float* Vs = Kt + 64 * FP;
    float* Ps = Vs + 64 * FP;
    int*  msk = (int*)(Ps + 64 * FP);

    const int qb = blockIdx.x;
    const int h  = blockIdx.y;
    const int b  = blockIdx.z;

    const float* Qg = g_q + ((size_t)(b * H_ + h)) * S_ * DH_;
    const float* Kg = g_k + ((size_t)(b * H_ + h)) * S_ * DH_;
    const float* Vg = g_v + ((size_t)(b * H_ + h)) * S_ * DH_;

    const int t  = threadIdx.x;
    const int tx = t & 15;
    const int ty = t >> 4;
    const int lrow = t >> 2;
    const int lq   = t & 3;

#pragma unroll
    for (int i = 0; i < 4; i++) {
        const int dh0 = 4 * (lq + 4 * i);
        float4 q4 = *(const float4*)(Qg + (size_t)(qb * 64 + lrow) * DH_ + dh0);
        Qt[(dh0 + 0) * FP + lrow] = q4.x;
        Qt[(dh0 + 1) * FP + lrow] = q4.y;
        Qt[(dh0 + 2) * FP + lrow] = q4.z;
        Qt[(dh0 + 3) * FP + lrow] = q4.w;
    }

    float m_i[4], l_i[4], o_acc[4][4];
#pragma unroll
    for (int i = 0; i < 4; i++) {
        m_i[i] = -1e30f; l_i[i] = 0.f;
#pragma unroll
        for (int j = 0; j < 4; j++) o_acc[i][j] = 0.f;
    }

    for (int kb = 0; kb < S_ / 64; kb++) {
        __syncthreads();
#pragma unroll
        for (int i = 0; i < 4; i++) {
            const int dh0 = 4 * (lq + 4 * i);
            float4 k4 = *(const float4*)(Kg + (size_t)(kb * 64 + lrow) * DH_ + dh0);
            Kt[(dh0 + 0) * FP + lrow] = k4.x;
            Kt[(dh0 + 1) * FP + lrow] = k4.y;
            Kt[(dh0 + 2) * FP + lrow] = k4.z;
            Kt[(dh0 + 3) * FP + lrow] = k4.w;
            float4 v4 = *(const float4*)(Vg + (size_t)(kb * 64 + lrow) * DH_ + dh0);
            *(float4*)&Vs[lrow * FP + dh0] = v4;
        }
        if (t < 64) msk[t] = mask[b * S_ + kb * 64 + t];
        __syncthreads();

        float s[4][4];
#pragma unroll
        for (int i = 0; i < 4; i++)
#pragma unroll
            for (int j = 0; j < 4; j++) s[i][j] = 0.f;
#pragma unroll 8
        for (int kk = 0; kk < 64; kk++) {
            float4 qv = *(const float4*)&Qt[kk * FP + (ty << 2)];
            float4 kv = *(const float4*)&Kt[kk * FP + (tx << 2)];
            s[0][0] += qv.x * kv.x; s[0][1] += qv.x * kv.y;
            s[0][2] += qv.x * kv.z; s[0][3] += qv.x * kv.w;
            s[1][0] += qv.y * kv.x; s[1][1] += qv.y * kv.y;
            s[1][2] += qv.y * kv.z; s[1][3] += qv.y * kv.w;
            s[2][0] += qv.z * kv.x; s[2][1] += qv.z * kv.y;
            s[2][2] += qv.z * kv.z; s[2][3] += qv.z * kv.w;
            s[3][0] += qv.w * kv.x; s[3][1] += qv.w * kv.y;
            s[3][2] += qv.w * kv.z; s[3][3] += qv.w * kv.w;
        }

#pragma unroll
        for (int j = 0; j < 4; j++) {
            const bool ok = msk[(tx << 2) + j] != 0;
#pragma unroll
            for (int i = 0; i < 4; i++)
                s[i][j] = ok ? s[i][j] * 0.125f : -1e9f;
        }

#pragma unroll
        for (int i = 0; i < 4; i++) {
            float rmax = fmaxf(fmaxf(s[i][0], s[i][1]), fmaxf(s[i][2], s[i][3]));
#pragma unroll
            for (int d = 1; d <= 8; d <<= 1)
                rmax = fmaxf(rmax, __shfl_xor_sync(0xffffffffu, rmax, d));
            const float mnew  = fmaxf(m_i[i], rmax);
            const float alpha = __expf(m_i[i] - mnew);
            float rsum = 0.f;
#pragma unroll
            for (int j = 0; j < 4; j++) {
                s[i][j] = __expf(s[i][j] - mnew);
                rsum += s[i][j];
            }
#pragma unroll
            for (int d = 1; d <= 8; d <<= 1)
                rsum += __shfl_xor_sync(0xffffffffu, rsum, d);
            l_i[i] = l_i[i] * alpha + rsum;
            m_i[i] = mnew;
#pragma unroll
            for (int j = 0; j < 4; j++) o_acc[i][j] *= alpha;
            *(float4*)&Ps[((ty << 2) + i) * FP + (tx << 2)] =
                make_float4(s[i][0], s[i][1], s[i][2], s[i][3]);
        }
        __syncthreads();

#pragma unroll 8
        for (int jj = 0; jj < 64; jj++) {
            const float4 vv = *(const float4*)&Vs[jj * FP + (tx << 2)];
            const float p0 = Ps[((ty << 2) + 0) * FP + jj];
            const float p1 = Ps[((ty << 2) + 1) * FP + jj];
            const float p2 = Ps[((ty << 2) + 2) * FP + jj];
            const float p3 = Ps[((ty << 2) + 3) * FP + jj];
            o_acc[0][0] += p0 * vv.x; o_acc[0][1] += p0 * vv.y;
            o_acc[0][2] += p0 * vv.z; o_acc[0][3] += p0 * vv.w;
            o_acc[1][0] += p1 * vv.x; o_acc[1][1] += p1 * vv.y;
            o_acc[1][2] += p1 * vv.z; o_acc[1][3] += p1 * vv.w;
            o_acc[2][0] += p2 * vv.x; o_acc[2][1] += p2 * vv.y;
            o_acc[2][2] += p2 * vv.z; o_acc[2][3] += p2 * vv.w;
            o_acc[3][0] += p3 * vv.x; o_acc[3][1] += p3 * vv.y;
            o_acc[3][2] += p3 * vv.z; o_acc[3][3] += p3 * vv.w;
        }
    }

#pragma unroll
    for (int i = 0; i < 4; i++) {
        const float inv = 1.f / l_i[i];
        const int sg = qb * 64 + (ty << 2) + i;
#pragma unroll
        for (int j = 0; j < 4; j++) {
            out[((size_t)(b * S_ + sg)) * D_ + h * DH_ + (tx << 2) + j] =
                o_acc[i][j] * inv;
        }
    }
}

// ---------------------------------------------------------------------------
// Launch
// ---------------------------------------------------------------------------
extern "C" void kernel_launch(void* const* d_in, const int* in_sizes, int n_in,
                              void* d_out, int out_size)
{
    (void)in_sizes; (void)n_in; (void)out_size;
    const float* x    = (const float*)d_in[0];
    const int*   mask = (const int*)  d_in[1];
    const float* Wq   = (const float*)d_in[2];
    const float* bq   = (const float*)d_in[3];
    const float* Wk   = (const float*)d_in[4];
    const float* bk   = (const float*)d_in[5];
    const float* Wv   = (const float*)d_in[6];
    const float* bv   = (const float*)d_in[7];
    const float* Wo   = (const float*)d_in[8];
    const float* bo   = (const float*)d_in[9];
    float* out = (float*)d_out;

    float *qp, *kp, *vp, *ap;
    cudaGetSymbolAddress((void**)&qp, g_q);
    cudaGetSymbolAddress((void**)&kp, g_k);
    cudaGetSymbolAddress((void**)&vp, g_v);
    cudaGetSymbolAddress((void**)&ap, g_att);

    const int flash_smem = (4 * 64 * FP) * 4 + 64 * 4;  // 69888 bytes
    static int attr_done = 0;
    if (!attr_done) {
        cudaFuncSetAttribute(flash_kernel,
                             cudaFuncAttributeMaxDynamicSharedMemorySize, flash_smem);
        attr_done = 1;
    }

    dim3 gg(D_ / 128, N_ / 128);   // (8, 32)
    gemm_mma_tf32<<<gg, 256>>>(x, Wq, bq, qp, 1);
    gemm_mma_tf32<<<gg, 256>>>(x, Wk, bk, kp, 1);
    gemm_mma_tf32<<<gg, 256>>>(x, Wv, bv, vp, 1);

    flash_kernel<<<dim3(S_ / 64, H_, B_), 256, flash_smem>>>(mask, ap);

    gemm_mma_tf32<<<gg, 256>>>(ap, Wo, bo, out, 0);
}